// round 7
// baseline (speedup 1.0000x reference)
#include <cuda_runtime.h>
#include <cuda_bf16.h>
#include <cuda_fp8.h>
#include <cstdint>
#include <cstddef>

// ---------------------------------------------------------------------------
// Problem constants.  ALL in/out buffers are FLOAT32 carriers of bf16 values
// (harness upconverts the JAX bf16 arrays to numpy float32).
// ---------------------------------------------------------------------------
#define NROWS 32768
#define KDIM  2048
#define ODIM  2048

// GEMM tiling (sm80-style mma.sync path — plain sm_100 target, no tcgen05).
// Legacy HMMA rate measured at ~512 bf16 MAC/cyc/SM; mainloop is pipe-bound.
#define TM 128
#define TN 256
#define KC 64
#define STAGES 3
#define NCHUNK (KDIM / KC)      // 32
#define THREADS 256             // 8 warps: 2 (M) x 4 (N), warp tile 64x64

// Padded-linear smem: 128B data + 16B pad per row -> conflict-free ldmatrix
#define RS 144
#define STAGE_A_BYTES (TM * RS)
#define STAGE_B_BYTES (TN * RS)
#define STAGE_BYTES   (STAGE_A_BYTES + STAGE_B_BYTES)
#define SMEM_DYN      (STAGES * STAGE_BYTES)            // 165888

// bf16 scratch for converted W only (8 MB). x is quantized inline in the GEMM.
__device__ __nv_bfloat16 g_wb[(size_t)ODIM * KDIM];

// ---------------------------------------------------------------------------
// helpers
// ---------------------------------------------------------------------------
__device__ __forceinline__ uint32_t smem_u32(const void* p) {
    uint32_t a;
    asm("{ .reg .u64 t; cvta.to.shared.u64 t, %1; cvt.u32.u64 %0, t; }"
        : "=r"(a) : "l"(p));
    return a;
}

__device__ __forceinline__ void cp16(uint32_t dst_smem, const void* src) {
    asm volatile("cp.async.cg.shared.global [%0], [%1], 16;"
                 :: "r"(dst_smem), "l"(__cvta_generic_to_global(src)) : "memory");
}

__device__ __forceinline__ void ldsm4(uint32_t (&r)[4], uint32_t addr) {
    asm volatile("ldmatrix.sync.aligned.m8n8.x4.shared.b16 {%0,%1,%2,%3}, [%4];"
                 : "=r"(r[0]), "=r"(r[1]), "=r"(r[2]), "=r"(r[3]) : "r"(addr));
}

__device__ __forceinline__ void mma16816(float (&d)[4], const uint32_t (&a)[4],
                                         uint32_t b0, uint32_t b1) {
    asm volatile(
        "mma.sync.aligned.m16n8k16.row.col.f32.bf16.bf16.f32 "
        "{%0,%1,%2,%3}, {%4,%5,%6,%7}, {%8,%9}, {%0,%1,%2,%3};"
        : "+f"(d[0]), "+f"(d[1]), "+f"(d[2]), "+f"(d[3])
        : "r"(a[0]), "r"(a[1]), "r"(a[2]), "r"(a[3]), "r"(b0), "r"(b1));
}

// Reference-exact quantize-dequant of one element:
// xs = bf16(bf16(x)/bf16(scale)); q = fp8_e4m3(xs); dq = bf16(q)*bf16(scale)
// (input x is bf16-representable, so the leading bf16() is the identity)
__device__ __forceinline__ __nv_bfloat16 qdq(float v, float sbf, __nv_bfloat16 sb) {
    float xs = __bfloat162float(__float2bfloat16(v / sbf));
    __nv_fp8_storage_t q = __nv_cvt_float_to_fp8(xs, __NV_SATFINITE, __NV_E4M3);
    __half_raw hr = __nv_cvt_fp8_to_halfraw(q, __NV_E4M3);
    return __hmul(__float2bfloat16(__half2float(__half(hr))), sb);
}

// ---------------------------------------------------------------------------
// Kernel 1: W f32 -> bf16 (8 MB out; ~8us)
// ---------------------------------------------------------------------------
__global__ void __launch_bounds__(256) wconv_kernel(const float4* __restrict__ w,
                                                    uint2* __restrict__ wb, long n4) {
    long i = (long)blockIdx.x * blockDim.x + threadIdx.x;
    long stride = (long)gridDim.x * blockDim.x;
    for (; i < n4; i += stride) {
        float4 v = w[i];
        __nv_bfloat162 p0 = __halves2bfloat162(__float2bfloat16(v.x),
                                               __float2bfloat16(v.y));
        __nv_bfloat162 p1 = __halves2bfloat162(__float2bfloat16(v.z),
                                               __float2bfloat16(v.w));
        wb[i] = make_uint2(*reinterpret_cast<uint32_t*>(&p0),
                           *reinterpret_cast<uint32_t*>(&p1));
    }
}

// ---------------------------------------------------------------------------
// Kernel 2: fused quant + GEMM
// out[m,o] = f32( bf16(sum_k qdq(x[m,k]) * wb[o,k]) +bf16 bf16(bias[o]) )
// A: f32 LDG -> inline quant -> bf16 STS (software-pipelined, distance 1)
// B: cp.async bf16 (distance 2), 3-stage ring, mma.sync mainloop.
// ---------------------------------------------------------------------------
__device__ __forceinline__ void ldgA(float4 (&buf)[4][2], const float* __restrict__ x,
                                     int m0, int k0, int tid) {
#pragma unroll
    for (int t = 0; t < 4; t++) {
        int u = tid + t * THREADS;
        int row = u >> 3, c = u & 7;
        const float4* p = reinterpret_cast<const float4*>(
            x + (size_t)(m0 + row) * KDIM + (size_t)(k0 + c * 8));
        buf[t][0] = p[0];
        buf[t][1] = p[1];
    }
}

__device__ __forceinline__ void stsA(const float4 (&buf)[4][2], char* smem,
                                     size_t stage_off, int tid,
                                     float sbf, __nv_bfloat16 sb) {
#pragma unroll
    for (int t = 0; t < 4; t++) {
        int u = tid + t * THREADS;
        int row = u >> 3, c = u & 7;
        const float* f = reinterpret_cast<const float*>(&buf[t][0]);
        uint32_t pk[4];
#pragma unroll
        for (int p = 0; p < 4; p++) {
            __nv_bfloat162 v = __halves2bfloat162(qdq(f[2 * p], sbf, sb),
                                                  qdq(f[2 * p + 1], sbf, sb));
            pk[p] = *reinterpret_cast<uint32_t*>(&v);
        }
        *reinterpret_cast<uint4*>(smem + stage_off + (size_t)(row * RS + c * 16)) =
            make_uint4(pk[0], pk[1], pk[2], pk[3]);
    }
}

__device__ __forceinline__ void loadB(uint32_t st, const __nv_bfloat16* W,
                                      int n0, int k0, int tid) {
#pragma unroll
    for (int t = 0; t < 8; t++) {
        int u = tid + t * THREADS;
        int row = u >> 3, c = u & 7;
        cp16(st + STAGE_A_BYTES + (uint32_t)(row * RS + c * 16),
             W + (size_t)(n0 + row) * KDIM + (size_t)(k0 + c * 8));
    }
}

__global__ void __launch_bounds__(THREADS, 1) gemm_kernel(
    const float* __restrict__ x,
    const __nv_bfloat16* __restrict__ W,
    const float* __restrict__ bias,
    const float* __restrict__ scale,
    float* __restrict__ out) {
    extern __shared__ __align__(128) char smem_raw[];
    const uint32_t sbase = smem_u32(smem_raw);

    const int tid = threadIdx.x;
    const int wid = tid >> 5, lane = tid & 31;
    const int wm = wid >> 2;
    const int wn = wid & 3;
    const int n0 = (int)(blockIdx.x & 7) * TN;   // N fastest: x-tile L2 reuse
    const int m0 = (int)(blockIdx.x >> 3) * TM;

    const __nv_bfloat16 sb = __float2bfloat16(scale[0]);
    const float sbf = __bfloat162float(sb);

    const int lrow = lane & 15;
    const int lhalf = lane >> 4;
    const uint32_t abase = (uint32_t)((wm * 64 + lrow) * RS + lhalf * 16);
    const uint32_t bbase = (uint32_t)((wn * 64 + lrow) * RS + lhalf * 16);

    float acc[4][8][4];
#pragma unroll
    for (int i = 0; i < 4; i++)
#pragma unroll
        for (int j = 0; j < 8; j++)
#pragma unroll
            for (int e = 0; e < 4; e++) acc[i][j][e] = 0.0f;

    float4 abuf[4][2];

    // Prologue: A0 quantized into stage0; B0,B1 in flight.
    ldgA(abuf, x, m0, 0, tid);
    stsA(abuf, smem_raw, 0, tid, sbf, sb);
    loadB(sbase + 0 * STAGE_BYTES, W, n0, 0 * KC, tid);
    asm volatile("cp.async.commit_group;" ::: "memory");
    loadB(sbase + 1 * STAGE_BYTES, W, n0, 1 * KC, tid);
    asm volatile("cp.async.commit_group;" ::: "memory");

    for (int i = 0; i < NCHUNK; i++) {
        if (i < NCHUNK - 1) asm volatile("cp.async.wait_group 1;" ::: "memory");
        else                asm volatile("cp.async.wait_group 0;" ::: "memory");
        __syncthreads();   // B_i + A_i visible; stages (i+1)%3,(i+2)%3 recyclable

        if (i + 2 < NCHUNK) {
            loadB(sbase + ((i + 2) % STAGES) * STAGE_BYTES, W, n0, (i + 2) * KC, tid);
            asm volatile("cp.async.commit_group;" ::: "memory");
        }
        if (i + 1 < NCHUNK)
            ldgA(abuf, x, m0, (i + 1) * KC, tid);   // ~3000cyc slack before use

        const uint32_t stA = sbase + (i % STAGES) * STAGE_BYTES;
        const uint32_t stB = stA + STAGE_A_BYTES;
#pragma unroll
        for (int ks = 0; ks < 4; ks++) {
            uint32_t a[4][4], b[4][4];
#pragma unroll
            for (int mf = 0; mf < 4; mf++)
                ldsm4(a[mf], stA + abase + (uint32_t)(mf * 16 * RS + ks * 32));
#pragma unroll
            for (int nt = 0; nt < 4; nt++)
                ldsm4(b[nt], stB + bbase + (uint32_t)(nt * 16 * RS + ks * 32));
#pragma unroll
            for (int mf = 0; mf < 4; mf++)
#pragma unroll
                for (int nt = 0; nt < 4; nt++) {
                    mma16816(acc[mf][2 * nt + 0], a[mf], b[nt][0], b[nt][2]);
                    mma16816(acc[mf][2 * nt + 1], a[mf], b[nt][1], b[nt][3]);
                }
        }

        if (i + 1 < NCHUNK)
            stsA(abuf, smem_raw, (size_t)((i + 1) % STAGES) * STAGE_BYTES,
                 tid, sbf, sb);   // before next iteration's __syncthreads
    }

    // Epilogue: f32 acc -> bf16, +bf16 bias, upconvert to f32 store.
    const int qrow = lane >> 2;
    const int qcol = (lane & 3) * 2;
#pragma unroll
    for (int mf = 0; mf < 4; mf++) {
#pragma unroll
        for (int nf = 0; nf < 8; nf++) {
            int col = n0 + wn * 64 + nf * 8 + qcol;
            __nv_bfloat16 b0 = __float2bfloat16(bias[col]);
            __nv_bfloat16 b1 = __float2bfloat16(bias[col + 1]);
            size_t r0 = (size_t)(m0 + wm * 64 + mf * 16 + qrow);
            float2 v0 = make_float2(
                __bfloat162float(__hadd(__float2bfloat16(acc[mf][nf][0]), b0)),
                __bfloat162float(__hadd(__float2bfloat16(acc[mf][nf][1]), b1)));
            float2 v1 = make_float2(
                __bfloat162float(__hadd(__float2bfloat16(acc[mf][nf][2]), b0)),
                __bfloat162float(__hadd(__float2bfloat16(acc[mf][nf][3]), b1)));
            *reinterpret_cast<float2*>(out + r0 * ODIM + col) = v0;
            *reinterpret_cast<float2*>(out + (r0 + 8) * ODIM + col) = v1;
        }
    }
}

// ---------------------------------------------------------------------------
// kernel_launch — inputs identified BY SIZE; all buffers FLOAT32
// ---------------------------------------------------------------------------
extern "C" void kernel_launch(void* const* d_in, const int* in_sizes, int n_in,
                              void* d_out, int out_size) {
    const float* x    = nullptr;
    const float* w    = nullptr;
    const float* bias = nullptr;
    const float* scale = nullptr;
    for (int i = 0; i < n_in; i++) {
        long s = (long)in_sizes[i];
        if (s == (long)NROWS * KDIM)      x     = (const float*)d_in[i];
        else if (s == (long)ODIM * KDIM)  w     = (const float*)d_in[i];
        else if (s == (long)ODIM)         bias  = (const float*)d_in[i];
        else if (s == 1)                  scale = (const float*)d_in[i];
    }
    float* out = (float*)d_out;

    void* wb_ptr = nullptr;
    cudaGetSymbolAddress(&wb_ptr, g_wb);

    wconv_kernel<<<1024, 256>>>((const float4*)w, (uint2*)wb_ptr,
                                (long)ODIM * KDIM / 4);

    cudaFuncSetAttribute(gemm_kernel, cudaFuncAttributeMaxDynamicSharedMemorySize,
                         SMEM_DYN);
    gemm_kernel<<<(NROWS / TM) * (ODIM / TN), THREADS, SMEM_DYN>>>(
        x, (const __nv_bfloat16*)wb_ptr, bias, scale, out);
}

// round 8
// speedup vs baseline: 1.6319x; 1.6319x over previous
#include <cuda_runtime.h>
#include <cuda_bf16.h>
#include <cuda_fp8.h>
#include <cstdint>
#include <cstddef>

// ---------------------------------------------------------------------------
// Problem constants.  ALL in/out buffers are FLOAT32 carriers of bf16 values.
// ---------------------------------------------------------------------------
#define NROWS 32768
#define KDIM  2048
#define ODIM  2048

// GEMM tiling: 128x128 CTA tile, 256 threads, 2 CTAs/SM (4 warps/SMSP).
#define TM 128
#define TN 128
#define KC 64
#define STAGES 3
#define NCHUNK (KDIM / KC)      // 32
#define THREADS 256             // 8 warps: 2 (M) x 4 (N), warp tile 64x32

// Padded-linear smem: 128B data + 16B pad per row -> conflict-free ldmatrix
#define RS 144
#define STAGE_A_BYTES (TM * RS)                         // 18432
#define STAGE_B_BYTES (TN * RS)                         // 18432
#define STAGE_BYTES   (STAGE_A_BYTES + STAGE_B_BYTES)   // 36864
#define SMEM_DYN      (STAGES * STAGE_BYTES)            // 110592 (x2 CTAs = 216KB)

// bf16 scratch: quantized x (134MB) and converted W (8MB)
__device__ __nv_bfloat16 g_xq[(size_t)NROWS * KDIM];
__device__ __nv_bfloat16 g_wb[(size_t)ODIM * KDIM];

// ---------------------------------------------------------------------------
// helpers
// ---------------------------------------------------------------------------
__device__ __forceinline__ uint32_t smem_u32(const void* p) {
    uint32_t a;
    asm("{ .reg .u64 t; cvta.to.shared.u64 t, %1; cvt.u32.u64 %0, t; }"
        : "=r"(a) : "l"(p));
    return a;
}

__device__ __forceinline__ void cp16(uint32_t dst_smem, const void* src) {
    asm volatile("cp.async.cg.shared.global [%0], [%1], 16;"
                 :: "r"(dst_smem), "l"(__cvta_generic_to_global(src)) : "memory");
}

__device__ __forceinline__ void ldsm4(uint32_t (&r)[4], uint32_t addr) {
    asm volatile("ldmatrix.sync.aligned.m8n8.x4.shared.b16 {%0,%1,%2,%3}, [%4];"
                 : "=r"(r[0]), "=r"(r[1]), "=r"(r[2]), "=r"(r[3]) : "r"(addr));
}

__device__ __forceinline__ void mma16816(float (&d)[4], const uint32_t (&a)[4],
                                         uint32_t b0, uint32_t b1) {
    asm volatile(
        "mma.sync.aligned.m16n8k16.row.col.f32.bf16.bf16.f32 "
        "{%0,%1,%2,%3}, {%4,%5,%6,%7}, {%8,%9}, {%0,%1,%2,%3};"
        : "+f"(d[0]), "+f"(d[1]), "+f"(d[2]), "+f"(d[3])
        : "r"(a[0]), "r"(a[1]), "r"(a[2]), "r"(a[3]), "r"(b0), "r"(b1));
}

// ---------------------------------------------------------------------------
// Kernel 1: quantize-dequant f32 x -> bf16 g_xq (reference-exact chain)
// ---------------------------------------------------------------------------
__global__ void __launch_bounds__(256) quant_kernel(const float4* __restrict__ x,
                                                    const float* __restrict__ scale,
                                                    uint2* __restrict__ xq, long n4) {
    __nv_bfloat16 sb = __float2bfloat16(scale[0]);
    float sbf = __bfloat162float(sb);
    long i = (long)blockIdx.x * blockDim.x + threadIdx.x;
    long stride = (long)gridDim.x * blockDim.x;
    for (; i < n4; i += stride) {
        float4 v = x[i];
        __nv_bfloat16 o[4];
        float in[4] = {v.x, v.y, v.z, v.w};
#pragma unroll
        for (int e = 0; e < 4; e++) {
            float xb = __bfloat162float(__float2bfloat16(in[e]));
            float xs = __bfloat162float(__float2bfloat16(xb / sbf));
            __nv_fp8_storage_t q = __nv_cvt_float_to_fp8(xs, __NV_SATFINITE, __NV_E4M3);
            __half_raw hr = __nv_cvt_fp8_to_halfraw(q, __NV_E4M3);
            o[e] = __hmul(__float2bfloat16(__half2float(__half(hr))), sb);
        }
        __nv_bfloat162 p0 = __halves2bfloat162(o[0], o[1]);
        __nv_bfloat162 p1 = __halves2bfloat162(o[2], o[3]);
        xq[i] = make_uint2(*reinterpret_cast<uint32_t*>(&p0),
                           *reinterpret_cast<uint32_t*>(&p1));
    }
}

// Kernel 1b: W f32 -> bf16
__global__ void __launch_bounds__(256) wconv_kernel(const float4* __restrict__ w,
                                                    uint2* __restrict__ wb, long n4) {
    long i = (long)blockIdx.x * blockDim.x + threadIdx.x;
    long stride = (long)gridDim.x * blockDim.x;
    for (; i < n4; i += stride) {
        float4 v = w[i];
        __nv_bfloat162 p0 = __halves2bfloat162(__float2bfloat16(v.x),
                                               __float2bfloat16(v.y));
        __nv_bfloat162 p1 = __halves2bfloat162(__float2bfloat16(v.z),
                                               __float2bfloat16(v.w));
        wb[i] = make_uint2(*reinterpret_cast<uint32_t*>(&p0),
                           *reinterpret_cast<uint32_t*>(&p1));
    }
}

// ---------------------------------------------------------------------------
// Kernel 2: GEMM  out[m,o] = f32( bf16(sum_k xq[m,k]*wb[o,k]) +bf16 bias[o] )
// 128x128 CTA tile, 2 CTAs/SM for 4 warps/SMSP latency hiding.
// ---------------------------------------------------------------------------
__device__ __forceinline__ void load_chunk(uint32_t st, const __nv_bfloat16* A,
                                           const __nv_bfloat16* W,
                                           int m0, int n0, int k0, int tid) {
    // A: 128 rows x 8 16B-units = 1024 units, 4 per thread
#pragma unroll
    for (int t = 0; t < 4; t++) {
        int u = tid + t * THREADS;
        int row = u >> 3, c = u & 7;
        cp16(st + (uint32_t)(row * RS + c * 16),
             A + (size_t)(m0 + row) * KDIM + (size_t)(k0 + c * 8));
    }
    // B: 128 rows x 8 units = 1024 units, 4 per thread
#pragma unroll
    for (int t = 0; t < 4; t++) {
        int u = tid + t * THREADS;
        int row = u >> 3, c = u & 7;
        cp16(st + STAGE_A_BYTES + (uint32_t)(row * RS + c * 16),
             W + (size_t)(n0 + row) * KDIM + (size_t)(k0 + c * 8));
    }
}

__global__ void __launch_bounds__(THREADS, 2) gemm_kernel(
    const __nv_bfloat16* __restrict__ A,
    const __nv_bfloat16* __restrict__ W,
    const float* __restrict__ bias,
    float* __restrict__ out) {
    extern __shared__ __align__(128) char smem_raw[];
    const uint32_t sbase = smem_u32(smem_raw);

    const int tid = threadIdx.x;
    const int wid = tid >> 5, lane = tid & 31;
    const int wm = wid >> 2;         // 0..1  (M warp, 64 rows)
    const int wn = wid & 3;          // 0..3  (N warp, 32 cols)
    const int n0 = (int)(blockIdx.x & 15) * TN;   // N fastest: xq-tile L2 reuse
    const int m0 = (int)(blockIdx.x >> 4) * TM;

    const int lrow = lane & 15;
    const int lhalf = lane >> 4;
    const uint32_t abase = (uint32_t)((wm * 64 + lrow) * RS + lhalf * 16);
    const uint32_t bbase = (uint32_t)((wn * 32 + lrow) * RS + lhalf * 16);

    float acc[4][4][4];
#pragma unroll
    for (int i = 0; i < 4; i++)
#pragma unroll
        for (int j = 0; j < 4; j++)
#pragma unroll
            for (int e = 0; e < 4; e++) acc[i][j][e] = 0.0f;

    load_chunk(sbase + 0 * STAGE_BYTES, A, W, m0, n0, 0 * KC, tid);
    asm volatile("cp.async.commit_group;" ::: "memory");
    load_chunk(sbase + 1 * STAGE_BYTES, A, W, m0, n0, 1 * KC, tid);
    asm volatile("cp.async.commit_group;" ::: "memory");

    for (int i = 0; i < NCHUNK; i++) {
        if (i < NCHUNK - 1) asm volatile("cp.async.wait_group 1;" ::: "memory");
        else                asm volatile("cp.async.wait_group 0;" ::: "memory");
        __syncthreads();

        if (i + 2 < NCHUNK) {
            load_chunk(sbase + ((i + 2) % STAGES) * STAGE_BYTES, A, W,
                       m0, n0, (i + 2) * KC, tid);
            asm volatile("cp.async.commit_group;" ::: "memory");
        }

        const uint32_t stA = sbase + (i % STAGES) * STAGE_BYTES;
        const uint32_t stB = stA + STAGE_A_BYTES;
#pragma unroll
        for (int ks = 0; ks < 4; ks++) {
            uint32_t a[4][4], b[2][4];
#pragma unroll
            for (int mf = 0; mf < 4; mf++)
                ldsm4(a[mf], stA + abase + (uint32_t)(mf * 16 * RS + ks * 32));
#pragma unroll
            for (int nt = 0; nt < 2; nt++)
                ldsm4(b[nt], stB + bbase + (uint32_t)(nt * 16 * RS + ks * 32));
#pragma unroll
            for (int mf = 0; mf < 4; mf++)
#pragma unroll
                for (int nt = 0; nt < 2; nt++) {
                    mma16816(acc[mf][2 * nt + 0], a[mf], b[nt][0], b[nt][2]);
                    mma16816(acc[mf][2 * nt + 1], a[mf], b[nt][1], b[nt][3]);
                }
        }
    }

    // Epilogue: f32 acc -> bf16, +bf16 bias, upconvert to f32 store.
    const int qrow = lane >> 2;
    const int qcol = (lane & 3) * 2;
#pragma unroll
    for (int mf = 0; mf < 4; mf++) {
#pragma unroll
        for (int nf = 0; nf < 4; nf++) {
            int col = n0 + wn * 32 + nf * 8 + qcol;
            __nv_bfloat16 b0 = __float2bfloat16(bias[col]);
            __nv_bfloat16 b1 = __float2bfloat16(bias[col + 1]);
            size_t r0 = (size_t)(m0 + wm * 64 + mf * 16 + qrow);
            float2 v0 = make_float2(
                __bfloat162float(__hadd(__float2bfloat16(acc[mf][nf][0]), b0)),
                __bfloat162float(__hadd(__float2bfloat16(acc[mf][nf][1]), b1)));
            float2 v1 = make_float2(
                __bfloat162float(__hadd(__float2bfloat16(acc[mf][nf][2]), b0)),
                __bfloat162float(__hadd(__float2bfloat16(acc[mf][nf][3]), b1)));
            *reinterpret_cast<float2*>(out + r0 * ODIM + col) = v0;
            *reinterpret_cast<float2*>(out + (r0 + 8) * ODIM + col) = v1;
        }
    }
}

// ---------------------------------------------------------------------------
// kernel_launch — inputs identified BY SIZE; all buffers FLOAT32
// ---------------------------------------------------------------------------
extern "C" void kernel_launch(void* const* d_in, const int* in_sizes, int n_in,
                              void* d_out, int out_size) {
    const float* x    = nullptr;
    const float* w    = nullptr;
    const float* bias = nullptr;
    const float* scale = nullptr;
    for (int i = 0; i < n_in; i++) {
        long s = (long)in_sizes[i];
        if (s == (long)NROWS * KDIM)      x     = (const float*)d_in[i];
        else if (s == (long)ODIM * KDIM)  w     = (const float*)d_in[i];
        else if (s == (long)ODIM)         bias  = (const float*)d_in[i];
        else if (s == 1)                  scale = (const float*)d_in[i];
    }
    float* out = (float*)d_out;

    void* xq_ptr = nullptr;
    void* wb_ptr = nullptr;
    cudaGetSymbolAddress(&xq_ptr, g_xq);
    cudaGetSymbolAddress(&wb_ptr, g_wb);

    quant_kernel<<<4096, 256>>>((const float4*)x, scale, (uint2*)xq_ptr,
                                (long)NROWS * KDIM / 4);
    wconv_kernel<<<1024, 256>>>((const float4*)w, (uint2*)wb_ptr,
                                (long)ODIM * KDIM / 4);

    cudaFuncSetAttribute(gemm_kernel, cudaFuncAttributeMaxDynamicSharedMemorySize,
                         SMEM_DYN);
    gemm_kernel<<<(NROWS / TM) * (ODIM / TN), THREADS, SMEM_DYN>>>(
        (const __nv_bfloat16*)xq_ptr, (const __nv_bfloat16*)wb_ptr, bias, out);
}